// round 3
// baseline (speedup 1.0000x reference)
#include <cuda_runtime.h>
#include <cstdint>

// CategoryAdder: out[b,s,:] = inputs[b,s,:] + emb
//   emb = table[categories[b,s]]  if categories[b,s] != 0 AND s != mask_positions[b]
//         0                       otherwise
//
// B=64, S=2048, D=512, N_CAT=5000.
// NOTE: JAX without x64 silently makes "int64" arrays int32 -> read as int.
// Pure HBM-streaming: 256MB in + 256MB out; table (10MB) is L2-resident.

static constexpr int B = 64;
static constexpr int S = 2048;
static constexpr int D = 512;
static constexpr int D4 = D / 4;                                // 128 float4 per row
static constexpr long long NROWS = (long long)B * S;            // 131072
static constexpr long long NVEC  = NROWS * D4;                  // 16,777,216 float4

__global__ __launch_bounds__(256)
void category_adder_kernel(const float4* __restrict__ in,
                           const int* __restrict__ cat,
                           const int* __restrict__ mask_pos,
                           const float4* __restrict__ table,
                           float4* __restrict__ out)
{
    long long idx = (long long)blockIdx.x * blockDim.x + threadIdx.x;
    if (idx >= NVEC) return;

    long long row = idx >> 7;        // / D4
    int col = (int)(idx & 127);
    int b = (int)(row >> 11);        // / S
    int s = (int)(row & 2047);       // % S

    int c  = __ldg(&cat[row]);
    int mp = __ldg(&mask_pos[b]);

    float4 v = in[idx];
    if (c != 0 && s != mp) {
        float4 e = __ldg(&table[(long long)c * D4 + col]);
        v.x += e.x; v.y += e.y; v.z += e.z; v.w += e.w;
    }
    out[idx] = v;
}

extern "C" void kernel_launch(void* const* d_in, const int* in_sizes, int n_in,
                              void* d_out, int out_size)
{
    const float4* inputs  = (const float4*)d_in[0];
    const int*    cats    = (const int*)d_in[1];
    const int*    maskpos = (const int*)d_in[2];
    const float4* table   = (const float4*)d_in[3];
    float4*       out     = (float4*)d_out;

    const int threads = 256;
    const unsigned nblk = (unsigned)((NVEC + threads - 1) / threads);   // 65536
    category_adder_kernel<<<nblk, threads>>>(inputs, cats, maskpos, table, out);
}

// round 4
// speedup vs baseline: 1.2678x; 1.2678x over previous
#include <cuda_runtime.h>
#include <cstdint>

// CategoryAdder: out[b,s,:] = inputs[b,s,:] + emb
//   emb = table[categories[b,s]]  if categories[b,s] != 0 AND s != mask_positions[b]
//         0                       otherwise
// B=64, S=2048, D=512, N_CAT=5000. categories/mask_positions are int32 on device.
//
// R4: 4 float4 per thread, block-strided, front-batched loads (MLP up),
//     streaming cache hints on the 512MB in/out stream to protect the
//     L2-resident 10MB table.

static constexpr int D4 = 128;                                   // float4 per row
static constexpr long long NVEC = (long long)64 * 2048 * D4;     // 16,777,216
static constexpr int THREADS = 256;
static constexpr int VPT = 4;                                    // float4 per thread
static constexpr int BLK_VEC = THREADS * VPT;                    // 1024 float4 / block

__global__ __launch_bounds__(THREADS)
void category_adder_kernel(const float4* __restrict__ in,
                           const int* __restrict__ cat,
                           const int* __restrict__ mask_pos,
                           const float4* __restrict__ table,
                           float4* __restrict__ out)
{
    const long long base = (long long)blockIdx.x * BLK_VEC + threadIdx.x;

    long long idx[VPT];
    long long trow[VPT];
    int  col[VPT];
    int  c[VPT], mp[VPT], s[VPT];
    float4 v[VPT];

    // Front-batch index math + scalar loads (cat broadcast within warp, L1/L2 hit)
    #pragma unroll
    for (int k = 0; k < VPT; k++) {
        idx[k] = base + (long long)k * THREADS;
        long long row = idx[k] >> 7;          // / D4
        col[k] = (int)(idx[k] & 127);
        int b  = (int)(row >> 11);            // / S
        s[k]   = (int)(row & 2047);           // % S
        c[k]   = __ldg(&cat[row]);
        mp[k]  = __ldg(&mask_pos[b]);
        trow[k] = (long long)c[k] * D4 + col[k];
    }

    // Front-batch the 4 streaming input loads (evict-first: read-once data)
    #pragma unroll
    for (int k = 0; k < VPT; k++)
        v[k] = __ldcs(&in[idx[k]]);

    // Table gathers (L2-resident) + add
    #pragma unroll
    for (int k = 0; k < VPT; k++) {
        if (c[k] != 0 && s[k] != mp[k]) {
            float4 e = __ldg(&table[trow[k]]);
            v[k].x += e.x; v[k].y += e.y; v[k].z += e.z; v[k].w += e.w;
        }
    }

    // Streaming stores (write-once)
    #pragma unroll
    for (int k = 0; k < VPT; k++)
        __stcs(&out[idx[k]], v[k]);
}

extern "C" void kernel_launch(void* const* d_in, const int* in_sizes, int n_in,
                              void* d_out, int out_size)
{
    const float4* inputs  = (const float4*)d_in[0];
    const int*    cats    = (const int*)d_in[1];
    const int*    maskpos = (const int*)d_in[2];
    const float4* table   = (const float4*)d_in[3];
    float4*       out     = (float4*)d_out;

    const unsigned nblk = (unsigned)(NVEC / BLK_VEC);   // 16384, exact
    category_adder_kernel<<<nblk, THREADS>>>(inputs, cats, maskpos, table, out);
}

// round 6
// speedup vs baseline: 1.2683x; 1.0004x over previous
#include <cuda_runtime.h>
#include <cstdint>

// CategoryAdder: out[b,s,:] = inputs[b,s,:] + emb
//   emb = table[categories[b,s]]  if categories[b,s] != 0 AND s != mask_positions[b]
//         0                       otherwise
// B=64, S=2048, D=512, N_CAT=5000. categories/mask_positions are int32 on device.
//
// R5 (resubmit; prior round was an infra failure): 8 float4 per thread,
// block-strided, fully front-batched loads. MLP per thread 4->8 to push
// DRAM% from 77% toward the streaming cap.

static constexpr int D4 = 128;                                   // float4 per row
static constexpr long long NVEC = (long long)64 * 2048 * D4;     // 16,777,216
static constexpr int THREADS = 256;
static constexpr int VPT = 8;                                    // float4 per thread
static constexpr int BLK_VEC = THREADS * VPT;                    // 2048 float4 / block

__global__ __launch_bounds__(THREADS)
void category_adder_kernel(const float4* __restrict__ in,
                           const int* __restrict__ cat,
                           const int* __restrict__ mask_pos,
                           const float4* __restrict__ table,
                           float4* __restrict__ out)
{
    const long long base = (long long)blockIdx.x * BLK_VEC + threadIdx.x;

    long long idx[VPT];
    long long trow[VPT];
    bool  add[VPT];
    float4 v[VPT];

    // Front-batch index math + scalar category/mask loads (L1-hit broadcasts)
    #pragma unroll
    for (int k = 0; k < VPT; k++) {
        idx[k] = base + (long long)k * THREADS;
        long long row = idx[k] >> 7;          // / D4
        int col = (int)(idx[k] & 127);
        int b  = (int)(row >> 11);            // / S
        int s  = (int)(row & 2047);           // % S
        int c  = __ldg(&cat[row]);
        int mp = __ldg(&mask_pos[b]);
        add[k] = (c != 0) && (s != mp);
        trow[k] = (long long)c * D4 + col;
    }

    // Front-batch 8 streaming input loads (evict-first: read-once data)
    #pragma unroll
    for (int k = 0; k < VPT; k++)
        v[k] = __ldcs(&in[idx[k]]);

    // Table gathers (L2-resident) + add
    #pragma unroll
    for (int k = 0; k < VPT; k++) {
        if (add[k]) {
            float4 e = __ldg(&table[trow[k]]);
            v[k].x += e.x; v[k].y += e.y; v[k].z += e.z; v[k].w += e.w;
        }
    }

    // Streaming stores (write-once)
    #pragma unroll
    for (int k = 0; k < VPT; k++)
        __stcs(&out[idx[k]], v[k]);
}

extern "C" void kernel_launch(void* const* d_in, const int* in_sizes, int n_in,
                              void* d_out, int out_size)
{
    const float4* inputs  = (const float4*)d_in[0];
    const int*    cats    = (const int*)d_in[1];
    const int*    maskpos = (const int*)d_in[2];
    const float4* table   = (const float4*)d_in[3];
    float4*       out     = (float4*)d_out;

    const unsigned nblk = (unsigned)(NVEC / BLK_VEC);   // 8192, exact
    category_adder_kernel<<<nblk, THREADS>>>(inputs, cats, maskpos, table, out);
}